// round 11
// baseline (speedup 1.0000x reference)
#include <cuda_runtime.h>
#include <cuda_fp16.h>
#include <cstdint>

// BTT dims: x (4096 x 4096), n=m=64, b=a=64, rank=8
// inner[B][n][m][r] = sum_b x[B, n*64+b] * R[n, b, m*8+r]
// out[B, m*64+a]    = sum_{n,r} inner[B][n][m][r] * L[m, n*8+r, a] + bias
// Chunked over B (8 x 512 rows), TWO inner buffers ping-pong; each launch
// runs pass1(chunk c) and pass2(chunk c-1) concurrently (no data dependence).

#define BTOT 4096
#define CHUNK 512
#define NCHUNK 8
#define INNER_SZ ((size_t)CHUNK * 64 * 64 * 8)   // 16M halves = 32 MB per buffer

#define P1_BLOCKS 256   // bt(4) x n(64)
#define P2_BLOCKS 128   // mq(16) x bt(8)

// ---------------- scratch (device globals; no allocation allowed) ----------
__device__ __half g_xh[(size_t)BTOT * 4096];       //  32 MB  x in fp16
__device__ __half g_w1t[(size_t)64 * 512 * 64];    //   4 MB  R^T: [n][j][b], j=m*8+r
__device__ __half g_w2t[(size_t)64 * 64 * 512];    //   4 MB  L^T: [m][a][k], k=n*8+r
__device__ __half g_inner[2 * INNER_SZ];           //  64 MB  two ping-pong buffers

// ---------------- conversion kernels ---------------------------------------
__global__ void conv_x(const float* __restrict__ x) {
    size_t i = (size_t)blockIdx.x * 256 + threadIdx.x;
    float4 v = ((const float4*)x)[i];
    __half2 h0 = __floats2half2_rn(v.x, v.y);
    __half2 h1 = __floats2half2_rn(v.z, v.w);
    uint2 u;
    u.x = *(unsigned*)&h0;
    u.y = *(unsigned*)&h1;
    *(uint2*)(g_xh + 4 * i) = u;
}

__global__ void conv_w1(const float* __restrict__ r) {
    int o = blockIdx.x * 256 + threadIdx.x;
    int b = o & 63, j = (o >> 6) & 511, n = o >> 15;
    g_w1t[o] = __float2half_rn(r[(size_t)(n * 64 + b) * 512 + j]);
}

__global__ void conv_w2(const float* __restrict__ l) {
    int o = blockIdx.x * 256 + threadIdx.x;
    int k = o & 511, a = (o >> 9) & 63, m = o >> 15;
    g_w2t[o] = __float2half_rn(l[(size_t)(m * 512 + k) * 64 + a]);
}

// ---------------- asm helpers ----------------------------------------------
__device__ __forceinline__ void mma16816(float* c, const unsigned* a, const unsigned* b) {
    asm volatile(
        "mma.sync.aligned.m16n8k16.row.col.f32.f16.f16.f32 "
        "{%0,%1,%2,%3}, {%4,%5,%6,%7}, {%8,%9}, {%0,%1,%2,%3};\n"
        : "+f"(c[0]), "+f"(c[1]), "+f"(c[2]), "+f"(c[3])
        : "r"(a[0]), "r"(a[1]), "r"(a[2]), "r"(a[3]), "r"(b[0]), "r"(b[1]));
}

__device__ __forceinline__ void ldsm4(unsigned& r0, unsigned& r1, unsigned& r2, unsigned& r3,
                                      unsigned addr) {
    asm volatile("ldmatrix.sync.aligned.m8n8.x4.shared.b16 {%0,%1,%2,%3}, [%4];"
                 : "=r"(r0), "=r"(r1), "=r"(r2), "=r"(r3) : "r"(addr));
}

__device__ __forceinline__ void cpa16(unsigned dst, const void* src) {
    asm volatile("cp.async.cg.shared.global [%0], [%1], 16;" :: "r"(dst), "l"(src));
}
__device__ __forceinline__ void cpcommit() { asm volatile("cp.async.commit_group;"); }
template <int N> __device__ __forceinline__ void cpwait() {
    asm volatile("cp.async.wait_group %0;" :: "n"(N));
}
__device__ __forceinline__ void cpwait_rt(int n) {
    switch (n) {
        case 0: cpwait<0>(); break;
        case 1: cpwait<1>(); break;
        case 2: cpwait<2>(); break;
        default: cpwait<3>(); break;
    }
}

// ---------------- pass 1 role: inner = X @ R --------------------------------
// blocks: bt(4) x n(64). A tile 128 rows x 64 b loaded once; 4 prefetched
// B stages of 128 j each. Smem: A 9216 halves + 4 x 9216 B = 92160 B.
#define P1_BOFF 9216
#define P1_BSTG 9216

__device__ __forceinline__ void pass1_role(int p, int chunk, __half* dsm) {
    const int bt = p & 3;
    const int n  = p >> 2;
    const int tid = threadIdx.x;
    const int grow0 = chunk * CHUNK + bt * 128;
    __half* inb = g_inner + (size_t)(chunk & 1) * INNER_SZ;
    unsigned sbase = (unsigned)__cvta_generic_to_shared(dsm);

    // prologue: group0 = A + B(jc=0); groups 1..3 = B(jc=1..3)
#pragma unroll
    for (int i = 0; i < 4; i++) {
        int q = tid + i * 256;          // 0..1023
        int row = q >> 3, c8 = q & 7;   // 128 rows x 8 x 16B
        cpa16(sbase + (row * 72 + c8 * 8) * 2,
              g_xh + (size_t)(grow0 + row) * 4096 + n * 64 + c8 * 8);
        cpa16(sbase + (P1_BOFF + row * 72 + c8 * 8) * 2,
              g_w1t + (size_t)(n * 512 + row) * 64 + c8 * 8);
    }
    cpcommit();
#pragma unroll
    for (int jc = 1; jc < 4; jc++) {
#pragma unroll
        for (int i = 0; i < 4; i++) {
            int q = tid + i * 256;
            int row = q >> 3, c8 = q & 7;
            cpa16(sbase + (P1_BOFF + jc * P1_BSTG + row * 72 + c8 * 8) * 2,
                  g_w1t + (size_t)(n * 512 + jc * 128 + row) * 64 + c8 * 8);
        }
        cpcommit();
    }

    const int warp = tid >> 5, lane = tid & 31;
    const int wm = warp >> 2, wn = warp & 3;   // 2 x 4 warp grid, warp tile 64x32
    const int g = lane >> 2, t = lane & 3;
    const int rl = lane & 7, sel = lane >> 3;
    const int offA = ((rl + (sel & 1) * 8) * 72 + (sel >> 1) * 8) * 2;
    const int offB = (((sel >> 1) * 8 + rl) * 72 + (sel & 1) * 8) * 2;

#pragma unroll
    for (int jc = 0; jc < 4; jc++) {
        cpwait_rt(3 - jc);
        __syncthreads();

        float acc[4][4][4];
#pragma unroll
        for (int mf = 0; mf < 4; mf++)
#pragma unroll
            for (int nf = 0; nf < 4; nf++)
#pragma unroll
                for (int c = 0; c < 4; c++) acc[mf][nf][c] = 0.f;

        unsigned bBase = sbase + (P1_BOFF + jc * P1_BSTG) * 2;
#pragma unroll
        for (int ks = 0; ks < 4; ks++) {
            const int k0 = ks * 16;
            unsigned af[4][4], bf[4][2];
#pragma unroll
            for (int mf = 0; mf < 4; mf++)
                ldsm4(af[mf][0], af[mf][1], af[mf][2], af[mf][3],
                      sbase + ((wm * 64 + mf * 16) * 72 + k0) * 2 + offA);
#pragma unroll
            for (int p2 = 0; p2 < 2; p2++)
                ldsm4(bf[2 * p2][0], bf[2 * p2][1], bf[2 * p2 + 1][0], bf[2 * p2 + 1][1],
                      bBase + ((wn * 32 + p2 * 16) * 72 + k0) * 2 + offB);
#pragma unroll
            for (int mf = 0; mf < 4; mf++)
#pragma unroll
                for (int nf = 0; nf < 4; nf++) mma16816(acc[mf][nf], af[mf], bf[nf]);
        }

        // epilogue: fp16 store to inner[Blocal][n][j]
#pragma unroll
        for (int mf = 0; mf < 4; mf++) {
            int lrow = bt * 128 + wm * 64 + mf * 16 + g;
#pragma unroll
            for (int nf = 0; nf < 4; nf++) {
                int jg = jc * 128 + wn * 32 + nf * 8 + 2 * t;
                size_t base = ((size_t)lrow * 64 + n) * 512 + jg;
                __half2 h0 = __floats2half2_rn(acc[mf][nf][0], acc[mf][nf][1]);
                *(__half2*)(inb + base) = h0;
                __half2 h1 = __floats2half2_rn(acc[mf][nf][2], acc[mf][nf][3]);
                *(__half2*)(inb + base + (size_t)8 * 64 * 512) = h1;   // row +8
            }
        }
    }
}

// ---------------- pass 2 role: out = inner @ L (4 m per CTA) ----------------
// blocks: mq(16) x bt(8). Out tile 64 x 256. K=512 in 16 chunks of 32,
// 2-stage cp.async pipeline, one __syncthreads per chunk.
#define P2_ASTG 10240
#define P2_BOFF 20480

__device__ __forceinline__ void p2_load(unsigned sbase, const __half* inb,
                                        int s, int kc, int bt, int mq, int tid) {
#pragma unroll
    for (int i = 0; i < 4; i++) {
        int q = tid + i * 256;          // 0..1023
        int row = q >> 4, nl = (q >> 2) & 3, mi = q & 3;
        cpa16(sbase + (s * P2_ASTG + (mi * 64 + row) * 40 + nl * 8) * 2,
              inb + (((size_t)(bt * 64 + row) * 64 + kc * 4 + nl) * 64 + mq * 4 + mi) * 8);
    }
#pragma unroll
    for (int i = 0; i < 4; i++) {
        int q = tid + i * 256;
        int mi = q >> 8, a = (q >> 2) & 63, kl = q & 3;
        cpa16(sbase + (P2_BOFF + s * P2_ASTG + (mi * 64 + a) * 40 + kl * 8) * 2,
              g_w2t + ((size_t)(mq * 4 + mi) * 64 + a) * 512 + kc * 32 + kl * 8);
    }
    cpcommit();
}

__device__ __forceinline__ void pass2_role(int q0, int chunk, __half* dsm,
                                           const float* __restrict__ bias,
                                           float* __restrict__ out) {
    const int mq = q0 & 15;
    const int bt = q0 >> 4;   // 0..7
    const int tid = threadIdx.x;
    const __half* inb = g_inner + (size_t)(chunk & 1) * INNER_SZ;
    unsigned sbase = (unsigned)__cvta_generic_to_shared(dsm);

    const int warp = tid >> 5, lane = tid & 31;
    const int wm = warp >> 2, wn = warp & 3;  // warp tile 32 rows x 64 cols (one m = wn)
    const int g = lane >> 2, t = lane & 3;
    const int rl = lane & 7, sel = lane >> 3;
    const int offA = ((rl + (sel & 1) * 8) * 40 + (sel >> 1) * 8) * 2;
    const int offB = (((sel >> 1) * 8 + rl) * 40 + (sel & 1) * 8) * 2;

    float acc[2][8][4];
#pragma unroll
    for (int mf = 0; mf < 2; mf++)
#pragma unroll
        for (int nf = 0; nf < 8; nf++)
#pragma unroll
            for (int c = 0; c < 4; c++) acc[mf][nf][c] = 0.f;

    p2_load(sbase, inb, 0, 0, bt, mq, tid);

    for (int kc = 0; kc < 16; kc++) {
        const int s = kc & 1;
        cpwait<0>();        // group kc complete (issued during compute of kc-1)
        __syncthreads();    // all warps done reading stage s^1 (prev contents)
        if (kc + 1 < 16) p2_load(sbase, inb, s ^ 1, kc + 1, bt, mq, tid);

        unsigned aBase = sbase + (s * P2_ASTG + wn * 64 * 40) * 2;
        unsigned bBase = sbase + ((P2_BOFF + s * P2_ASTG) + wn * 64 * 40) * 2;
#pragma unroll
        for (int ks = 0; ks < 2; ks++) {
            const int k0 = ks * 16;
            unsigned af[2][4], bf[8][2];
#pragma unroll
            for (int mf = 0; mf < 2; mf++)
                ldsm4(af[mf][0], af[mf][1], af[mf][2], af[mf][3],
                      aBase + ((wm * 32 + mf * 16) * 40 + k0) * 2 + offA);
#pragma unroll
            for (int p = 0; p < 4; p++)
                ldsm4(bf[2 * p][0], bf[2 * p][1], bf[2 * p + 1][0], bf[2 * p + 1][1],
                      bBase + ((p * 16) * 40 + k0) * 2 + offB);
#pragma unroll
            for (int mf = 0; mf < 2; mf++)
#pragma unroll
                for (int nf = 0; nf < 8; nf++) mma16816(acc[mf][nf], af[mf], bf[nf]);
        }
    }

    // epilogue: fp32 out + bias
#pragma unroll
    for (int mf = 0; mf < 2; mf++) {
        int row = chunk * CHUNK + bt * 64 + wm * 32 + mf * 16 + g;
#pragma unroll
        for (int nf = 0; nf < 8; nf++) {
            int col = (mq * 4 + wn) * 64 + nf * 8 + 2 * t;
            float b0 = bias[col], b1 = bias[col + 1];
            float2 v0 = make_float2(acc[mf][nf][0] + b0, acc[mf][nf][1] + b1);
            *(float2*)(out + (size_t)row * 4096 + col) = v0;
            float2 v1 = make_float2(acc[mf][nf][2] + b0, acc[mf][nf][3] + b1);
            *(float2*)(out + (size_t)(row + 8) * 4096 + col) = v1;
        }
    }
}

// ---------------- fused kernel: pass1(c1) || pass2(c2) ----------------------
__global__ __launch_bounds__(256) void btt_fused(int c1, int c2,
                                                 const float* __restrict__ bias,
                                                 float* __restrict__ out) {
    extern __shared__ __half dsm[];
    int p = blockIdx.x;
    if (p < P1_BLOCKS) {
        if (c1 >= 0) pass1_role(p, c1, dsm);
    } else {
        if (c2 >= 0) pass2_role(p - P1_BLOCKS, c2, dsm, bias, out);
    }
}

// ---------------- launch ----------------------------------------------------
extern "C" void kernel_launch(void* const* d_in, const int* in_sizes, int n_in,
                              void* d_out, int out_size) {
    const float* x    = (const float*)d_in[0];  // (4,1024,4096)
    const float* rw   = (const float*)d_in[1];  // (64,64,512)
    const float* lw   = (const float*)d_in[2];  // (64,512,64)
    const float* bias = (const float*)d_in[3];  // (4096)
    float* out = (float*)d_out;

    cudaFuncSetAttribute(btt_fused, cudaFuncAttributeMaxDynamicSharedMemorySize, 92160);

    conv_x<<<16384, 256>>>(x);
    conv_w1<<<8192, 256>>>(rw);
    conv_w2<<<8192, 256>>>(lw);
    for (int c = 0; c <= NCHUNK; c++) {
        int c1 = (c < NCHUNK) ? c : -1;
        int c2 = c - 1;   // -1 on first launch
        btt_fused<<<P1_BLOCKS + P2_BLOCKS, 256, 92160>>>(c1, c2, bias, out);
    }
}

// round 16
// speedup vs baseline: 1.4045x; 1.4045x over previous
#include <cuda_runtime.h>
#include <cuda_fp16.h>
#include <cstdint>

// BTT dims: x (4096 x 4096), n=m=64, b=a=64, rank=8
// inner[B][n][m][r] = sum_b x[B, n*64+b] * R[n, b, m*8+r]
// out[B, m*64+a]    = sum_{n,r} inner[B][n][m][r] * L[m, n*8+r, a] + bias
// Unchunked: inner is full-size; DRAM has headroom (measured 10-25%).

#define BTOT 4096

// ---------------- scratch (device globals; no allocation allowed) ----------
__device__ __half g_xh[(size_t)BTOT * 4096];            //  32 MB  x in fp16
__device__ __half g_w1t[(size_t)64 * 512 * 64];         //   4 MB  R^T: [n][j][b], j=m*8+r
__device__ __half g_w2t[(size_t)64 * 64 * 512];         //   4 MB  L^T: [m][a][k], k=n*8+r
__device__ __half g_inner[(size_t)BTOT * 64 * 64 * 8];  // 256 MB  [B][n][m][r]

// ---------------- conversion kernels ---------------------------------------
__global__ void conv_x(const float* __restrict__ x) {
    size_t i = (size_t)blockIdx.x * 256 + threadIdx.x;
    float4 v = ((const float4*)x)[i];
    __half2 h0 = __floats2half2_rn(v.x, v.y);
    __half2 h1 = __floats2half2_rn(v.z, v.w);
    uint2 u;
    u.x = *(unsigned*)&h0;
    u.y = *(unsigned*)&h1;
    *(uint2*)(g_xh + 4 * i) = u;
}

__global__ void conv_w(const float* __restrict__ r, const float* __restrict__ l) {
    int o = blockIdx.x * 256 + threadIdx.x;   // 0..4194303
    if (o < (1 << 21)) {
        int b = o & 63, j = (o >> 6) & 511, n = o >> 15;
        g_w1t[o] = __float2half_rn(r[(size_t)(n * 64 + b) * 512 + j]);
    } else {
        int o2 = o - (1 << 21);
        int k = o2 & 511, a = (o2 >> 9) & 63, m = o2 >> 15;
        g_w2t[o2] = __float2half_rn(l[(size_t)(m * 512 + k) * 64 + a]);
    }
}

// ---------------- asm helpers ----------------------------------------------
__device__ __forceinline__ void mma16816(float* c, const unsigned* a, const unsigned* b) {
    asm volatile(
        "mma.sync.aligned.m16n8k16.row.col.f32.f16.f16.f32 "
        "{%0,%1,%2,%3}, {%4,%5,%6,%7}, {%8,%9}, {%0,%1,%2,%3};\n"
        : "+f"(c[0]), "+f"(c[1]), "+f"(c[2]), "+f"(c[3])
        : "r"(a[0]), "r"(a[1]), "r"(a[2]), "r"(a[3]), "r"(b[0]), "r"(b[1]));
}

__device__ __forceinline__ void ldsm4(unsigned& r0, unsigned& r1, unsigned& r2, unsigned& r3,
                                      unsigned addr) {
    asm volatile("ldmatrix.sync.aligned.m8n8.x4.shared.b16 {%0,%1,%2,%3}, [%4];"
                 : "=r"(r0), "=r"(r1), "=r"(r2), "=r"(r3) : "r"(addr));
}

__device__ __forceinline__ void cpa16(unsigned dst, const void* src) {
    asm volatile("cp.async.cg.shared.global [%0], [%1], 16;" :: "r"(dst), "l"(src));
}
__device__ __forceinline__ void cpcommit() { asm volatile("cp.async.commit_group;"); }
template <int N> __device__ __forceinline__ void cpwait() {
    asm volatile("cp.async.wait_group %0;" :: "n"(N));
}

// ---------------- pass 1: inner = X @ R (2 j-tiles per CTA) -----------------
// Grid (jh 0..1, n 0..63, bt 0..31) = 4096 CTAs. A tile 128 rows x 64 b loaded
// once; two 128-wide j tiles of R^T, second prefetched while first computes.
// Dyn smem halves: A at 0, B0 at 9216, B1 at 18432 -> 55296 B.
#define P1_B0 9216
#define P1_B1 18432

__global__ __launch_bounds__(256) void btt_pass1() {
    extern __shared__ __half dsm[];
    const int jh = blockIdx.x;     // 0..1 -> j tiles {2jh, 2jh+1}
    const int n  = blockIdx.y;
    const int bt = blockIdx.z;     // 0..31, 128 rows each
    const int tid = threadIdx.x;
    const int grow0 = bt * 128;
    const int jbase = jh * 256;    // j offset of first tile (in j units of 1)
    unsigned sbase = (unsigned)__cvta_generic_to_shared(dsm);

    // group0 = A + B(tile0); group1 = B(tile1)
#pragma unroll
    for (int i = 0; i < 4; i++) {
        int q = tid + i * 256;          // 0..1023
        int row = q >> 3, c8 = q & 7;   // 128 rows x 8 x 16B
        cpa16(sbase + (row * 72 + c8 * 8) * 2,
              g_xh + (size_t)(grow0 + row) * 4096 + n * 64 + c8 * 8);
        cpa16(sbase + (P1_B0 + row * 72 + c8 * 8) * 2,
              g_w1t + (size_t)(n * 512 + jbase + row) * 64 + c8 * 8);
    }
    cpcommit();
#pragma unroll
    for (int i = 0; i < 4; i++) {
        int q = tid + i * 256;
        int row = q >> 3, c8 = q & 7;
        cpa16(sbase + (P1_B1 + row * 72 + c8 * 8) * 2,
              g_w1t + (size_t)(n * 512 + jbase + 128 + row) * 64 + c8 * 8);
    }
    cpcommit();

    const int warp = tid >> 5, lane = tid & 31;
    const int wm = warp >> 2, wn = warp & 3;   // 2 x 4 warp grid, warp tile 64x32
    const int g = lane >> 2, t = lane & 3;
    const int rl = lane & 7, sel = lane >> 3;
    const int offA = ((rl + (sel & 1) * 8) * 72 + (sel >> 1) * 8) * 2;
    const int offB = (((sel >> 1) * 8 + rl) * 72 + (sel & 1) * 8) * 2;

#pragma unroll
    for (int half = 0; half < 2; half++) {
        if (half == 0) cpwait<1>(); else cpwait<0>();
        __syncthreads();

        float acc[4][4][4];
#pragma unroll
        for (int mf = 0; mf < 4; mf++)
#pragma unroll
            for (int nf = 0; nf < 4; nf++)
#pragma unroll
                for (int c = 0; c < 4; c++) acc[mf][nf][c] = 0.f;

        unsigned bBase = sbase + (half == 0 ? P1_B0 : P1_B1) * 2;
#pragma unroll
        for (int ks = 0; ks < 4; ks++) {
            const int k0 = ks * 16;
            unsigned af[4][4], bf[4][2];
#pragma unroll
            for (int mf = 0; mf < 4; mf++)
                ldsm4(af[mf][0], af[mf][1], af[mf][2], af[mf][3],
                      sbase + ((wm * 64 + mf * 16) * 72 + k0) * 2 + offA);
#pragma unroll
            for (int p = 0; p < 2; p++)
                ldsm4(bf[2 * p][0], bf[2 * p][1], bf[2 * p + 1][0], bf[2 * p + 1][1],
                      bBase + ((wn * 32 + p * 16) * 72 + k0) * 2 + offB);
#pragma unroll
            for (int mf = 0; mf < 4; mf++)
#pragma unroll
                for (int nf = 0; nf < 4; nf++) mma16816(acc[mf][nf], af[mf], bf[nf]);
        }

        // epilogue: fp16 store to g_inner[B][n][j]  (j contiguous)
#pragma unroll
        for (int mf = 0; mf < 4; mf++) {
            int lrow = grow0 + wm * 64 + mf * 16 + g;
#pragma unroll
            for (int nf = 0; nf < 4; nf++) {
                int jg = jbase + half * 128 + wn * 32 + nf * 8 + 2 * t;
                size_t base = ((size_t)lrow * 64 + n) * 512 + jg;
                __half2 h0 = __floats2half2_rn(acc[mf][nf][0], acc[mf][nf][1]);
                *(__half2*)(g_inner + base) = h0;
                __half2 h1 = __floats2half2_rn(acc[mf][nf][2], acc[mf][nf][3]);
                *(__half2*)(g_inner + base + (size_t)8 * 64 * 512) = h1;   // row +8
            }
        }
    }
}

// ---------------- pass 2: out = inner @ L (4 m per CTA) --------------------
// Grid (mq 0..15, bt 0..63) = 1024 CTAs. Out tile 64 x 256. K=512 in 16
// chunks of 32, 2-stage cp.async pipeline, ONE __syncthreads per chunk:
//   wait<0> -> sync -> issue(kc+1) -> compute(kc)      (proven in R9)
// Layout (halves): A[s][mi][row][40] at s*10240; B at 20480 + s*10240.
#define P2_ASTG 10240
#define P2_BOFF 20480

__device__ __forceinline__ void p2_load(unsigned sbase, int s, int kc, int bt, int mq, int tid) {
#pragma unroll
    for (int i = 0; i < 4; i++) {
        int q = tid + i * 256;          // 0..1023
        int row = q >> 4, nl = (q >> 2) & 3, mi = q & 3;
        cpa16(sbase + (s * P2_ASTG + (mi * 64 + row) * 40 + nl * 8) * 2,
              g_inner + (((size_t)(bt * 64 + row) * 64 + kc * 4 + nl) * 64 + mq * 4 + mi) * 8);
    }
#pragma unroll
    for (int i = 0; i < 4; i++) {
        int q = tid + i * 256;
        int mi = q >> 8, a = (q >> 2) & 63, kl = q & 3;
        cpa16(sbase + (P2_BOFF + s * P2_ASTG + (mi * 64 + a) * 40 + kl * 8) * 2,
              g_w2t + ((size_t)(mq * 4 + mi) * 64 + a) * 512 + kc * 32 + kl * 8);
    }
    cpcommit();
}

__global__ __launch_bounds__(256) void btt_pass2(const float* __restrict__ bias,
                                                 float* __restrict__ out) {
    extern __shared__ __half dsm[];
    const int mq = blockIdx.x;
    const int bt = blockIdx.y;     // 0..63, 64 rows each
    const int tid = threadIdx.x;
    unsigned sbase = (unsigned)__cvta_generic_to_shared(dsm);

    const int warp = tid >> 5, lane = tid & 31;
    const int wm = warp >> 2, wn = warp & 3;  // warp tile 32 rows x 64 cols (one m = wn)
    const int g = lane >> 2, t = lane & 3;
    const int rl = lane & 7, sel = lane >> 3;
    const int offA = ((rl + (sel & 1) * 8) * 40 + (sel >> 1) * 8) * 2;
    const int offB = (((sel >> 1) * 8 + rl) * 40 + (sel & 1) * 8) * 2;

    float acc[2][8][4];
#pragma unroll
    for (int mf = 0; mf < 2; mf++)
#pragma unroll
        for (int nf = 0; nf < 8; nf++)
#pragma unroll
            for (int c = 0; c < 4; c++) acc[mf][nf][c] = 0.f;

    p2_load(sbase, 0, 0, bt, mq, tid);

    for (int kc = 0; kc < 16; kc++) {
        const int s = kc & 1;
        cpwait<0>();        // group kc complete (issued during compute of kc-1)
        __syncthreads();    // all warps done reading stage s (prev contents)
        if (kc + 1 < 16) p2_load(sbase, s ^ 1, kc + 1, bt, mq, tid);

        unsigned aBase = sbase + (s * P2_ASTG + wn * 64 * 40) * 2;
        unsigned bBase = sbase + ((P2_BOFF + s * P2_ASTG) + wn * 64 * 40) * 2;
#pragma unroll
        for (int ks = 0; ks < 2; ks++) {
            const int k0 = ks * 16;
            unsigned af[2][4], bf[8][2];
#pragma unroll
            for (int mf = 0; mf < 2; mf++)
                ldsm4(af[mf][0], af[mf][1], af[mf][2], af[mf][3],
                      aBase + ((wm * 32 + mf * 16) * 40 + k0) * 2 + offA);
#pragma unroll
            for (int p = 0; p < 4; p++)
                ldsm4(bf[2 * p][0], bf[2 * p][1], bf[2 * p + 1][0], bf[2 * p + 1][1],
                      bBase + ((p * 16) * 40 + k0) * 2 + offB);
#pragma unroll
            for (int mf = 0; mf < 2; mf++)
#pragma unroll
                for (int nf = 0; nf < 8; nf++) mma16816(acc[mf][nf], af[mf], bf[nf]);
        }
    }

    // epilogue: fp32 out + bias
#pragma unroll
    for (int mf = 0; mf < 2; mf++) {
        int row = bt * 64 + wm * 32 + mf * 16 + g;
#pragma unroll
        for (int nf = 0; nf < 8; nf++) {
            int col = (mq * 4 + wn) * 64 + nf * 8 + 2 * t;
            float b0 = bias[col], b1 = bias[col + 1];
            float2 v0 = make_float2(acc[mf][nf][0] + b0, acc[mf][nf][1] + b1);
            *(float2*)(out + (size_t)row * 4096 + col) = v0;
            float2 v1 = make_float2(acc[mf][nf][2] + b0, acc[mf][nf][3] + b1);
            *(float2*)(out + (size_t)(row + 8) * 4096 + col) = v1;
        }
    }
}

// ---------------- launch ----------------------------------------------------
extern "C" void kernel_launch(void* const* d_in, const int* in_sizes, int n_in,
                              void* d_out, int out_size) {
    const float* x    = (const float*)d_in[0];  // (4,1024,4096)
    const float* rw   = (const float*)d_in[1];  // (64,64,512)
    const float* lw   = (const float*)d_in[2];  // (64,512,64)
    const float* bias = (const float*)d_in[3];  // (4096)
    float* out = (float*)d_out;

    cudaFuncSetAttribute(btt_pass1, cudaFuncAttributeMaxDynamicSharedMemorySize, 55296);
    cudaFuncSetAttribute(btt_pass2, cudaFuncAttributeMaxDynamicSharedMemorySize, 81920);

    conv_x<<<16384, 256>>>(x);
    conv_w<<<16384, 256>>>(rw, lw);
    btt_pass1<<<dim3(2, 64, 32), 256, 55296>>>();
    btt_pass2<<<dim3(16, 64), 256, 81920>>>(bias, out);
}